// round 12
// baseline (speedup 1.0000x reference)
#include <cuda_runtime.h>

#define IMG    1024
#define OUTD   1016
#define TILE_W 128
#define TILE_H 48
#define IN_H   (TILE_H + 8)    // 56 input rows
#define HS     136             // smem row stride (floats)
#define NT     320
#define NW     (NT / 32)       // 10 warps
#define STRIPH 24              // output rows per strip
#define NSTEP  (STRIPH + 4)    // 28 D-rows per strip (24 outputs + 4 warmup)

__device__ __forceinline__ float4 ld4g(const float* __restrict__ img, int gr, int gc) {
    float4 v = make_float4(0.f, 0.f, 0.f, 0.f);
    if (gr < IMG) {
        const float* row = img + (size_t)gr * IMG;
        if (gc + 3 < IMG) {
            v = *(const float4*)(row + gc);
        } else {
            if (gc     < IMG) v.x = row[gc];
            if (gc + 1 < IMG) v.y = row[gc + 1];
            if (gc + 2 < IMG) v.z = row[gc + 2];
        }
    }
    return v;
}

// Horizontal 5-sum of one 136-col row into hrow[0..131].
// Lane ln computes h[4ln..4ln+3] from its own float4 + neighbor via 4 shuffles;
// lane 31 replaces the (garbage) shuffle result with direct halo loads and also
// produces h[128..131]. 4 shuffles total vs 12 in the previous version.
__device__ __forceinline__ void hrow_sum(const float* __restrict__ img, int gr,
                                         int gc0, float* hrow, int ln) {
    const unsigned m = 0xFFFFFFFFu;
    float4 v = ld4g(img, gr, gc0 + 4 * ln);
    float4 nb;
    nb.x = __shfl_down_sync(m, v.x, 1);
    nb.y = __shfl_down_sync(m, v.y, 1);
    nb.z = __shfl_down_sync(m, v.z, 1);
    nb.w = __shfl_down_sync(m, v.w, 1);
    float4 e = make_float4(0.f, 0.f, 0.f, 0.f);
    if (ln == 31) {
        nb = ld4g(img, gr, gc0 + 128);   // cols 128..131 (lane 31's neighbor)
        e  = ld4g(img, gr, gc0 + 132);   // cols 132..135
    }
    float h0 = (v.x + v.y) + (v.z + v.w) + nb.x;
    float h1 = h0 - v.x + nb.y;
    float h2 = h1 - v.y + nb.z;
    float h3 = h2 - v.z + nb.w;
    *(float4*)(hrow + 4 * ln) = make_float4(h0, h1, h2, h3);
    if (ln == 31) {                      // h[128..131] from cols 128..135
        float g0 = (nb.x + nb.y) + (nb.z + nb.w) + e.x;
        float g1 = g0 - nb.x + e.y;
        float g2 = g1 - nb.y + e.z;
        float g3 = g2 - nb.z + e.w;
        *(float4*)(hrow + 128) = make_float4(g0, g1, g2, g3);
    }
}

__global__ __launch_bounds__(NT, 3) void cov_kernel(
    const float* __restrict__ x, const float* __restrict__ y,
    float* __restrict__ out)
{
    extern __shared__ float sm[];
    float* hA = sm;              // [IN_H][HS] : horizontal 5-sums of x (read-only after P1)
    float* hB = sm + IN_H * HS;  // [IN_H][HS] : horizontal 5-sums of y

    const int bx  = blockIdx.x * TILE_W;
    const int by  = blockIdx.y * TILE_H;
    const int n   = blockIdx.z;
    const int tid = threadIdx.x;
    const int wid = tid >> 5;
    const int ln  = tid & 31;

    const size_t ibase = (size_t)n * IMG * IMG;
    const float* xp = x + ibase;
    const float* yp = y + ibase;

    // ---- Phase 1: global load + horizontal 5-sums for x and y ----
    for (int r = wid; r < IN_H; r += NW) {
        const int gr = by + r;
        hrow_sum(xp, gr, bx, hA + r * HS, ln);
        hrow_sum(yp, gr, bx, hB + r * HS, ln);
    }
    __syncthreads();   // the only barrier: hA/hB are read-only from here on

    // ---- Phase 2 (fused): vertical 5-sums, deviation product, horizontal 5-sum
    // of D via 3 warp shuffles, vertical 5-sum of that via register ring, direct
    // global store. wid = strip*5 + wseg; a warp owns 32 D-columns
    // qr = wseg*28 + ln (4-col shuffle halo between segments) and NSTEP D-rows.
    {
        const unsigned FULL = 0xFFFFFFFFu;
        const int strip = wid / 5;               // 0..1
        const int wseg  = wid % 5;
        const int p0    = strip * STRIPH;        // 0 or 24
        const int qr    = wseg * 28 + ln;        // nominal D column (0..139)
        const int q     = qr < 131 ? qr : 131;   // clamp for safe smem reads

        const float* cA = hA + q;
        const float* cB = hB + q;
        float rgA[5], rgB[5], rd[5];
        #pragma unroll
        for (int t = 0; t < 5; ++t) {
            rgA[t] = cA[(p0 + t) * HS];
            rgB[t] = cB[(p0 + t) * HS];
            rd[t]  = 0.f;
        }
        float sA = ((rgA[0] + rgA[1]) + (rgA[2] + rgA[3])) + rgA[4];
        float sB = ((rgB[0] + rgB[1]) + (rgB[2] + rgB[3])) + rgB[4];
        float vd = 0.f;

        const int  gc     = bx + q + 2;
        const bool gcok   = (gc < IMG);
        const int  rowlim = IMG - (by + p0 + 2);     // #valid center rows
        const float* xc = xp + (size_t)(by + p0 + 2) * IMG + gc;
        const float* yc = yp + (size_t)(by + p0 + 2) * IMG + gc;

        // output col = qr (lanes 0..27 only); output row oy = by + p0 + k - 4
        const bool jout = (ln < 28) && (qr < TILE_W) && (bx + qr < OUTD);
        const int  klim = min(NSTEP, OUTD - by - p0 + 4);   // oy < OUTD
        float* ob = out + (size_t)n * OUTD * OUTD + bx + qr;

        #pragma unroll
        for (int k = 0; k < NSTEP; ++k) {
            const bool ok = gcok && (k < rowlim);
            float xv = ok ? xc[(size_t)k * IMG] : 0.f;   // L2-hit center re-read
            float yv = ok ? yc[(size_t)k * IMG] : 0.f;
            float d  = (xv - sA * 0.04f) * (yv - sB * 0.04f);

            // horizontal 5-sum of D across lanes: d[q]+..+d[q+4] in 3 shuffles
            float a  = d + __shfl_down_sync(FULL, d, 1);
            float hd = a + __shfl_down_sync(FULL, a, 2)
                         + __shfl_down_sync(FULL, d, 4);

            vd += hd - rd[k % 5];
            rd[k % 5] = hd;

            if (k >= 4 && k < klim && jout)
                ob[(size_t)(by + p0 + k - 4) * OUTD] = vd * 0.04f;

            if (k < NSTEP - 1) {
                float nwA = cA[(p0 + k + 5) * HS];
                sA += nwA - rgA[k % 5];  rgA[k % 5] = nwA;
                float nwB = cB[(p0 + k + 5) * HS];
                sB += nwB - rgB[k % 5];  rgB[k % 5] = nwB;
            }
        }
    }
}

extern "C" void kernel_launch(void* const* d_in, const int* in_sizes, int n_in,
                              void* d_out, int out_size) {
    const float* x = (const float*)d_in[0];
    const float* y = (const float*)d_in[1];
    // d_in[2] = mean_mask (uniform 1/25, folded into the 0.04f constants)
    float* out = (float*)d_out;

    const int smem = 2 * IN_H * HS * (int)sizeof(float);   // 60928 B
    cudaFuncSetAttribute(cov_kernel, cudaFuncAttributeMaxDynamicSharedMemorySize, smem);

    dim3 grid((OUTD + TILE_W - 1) / TILE_W,    // 8
              (OUTD + TILE_H - 1) / TILE_H,    // 22
              16);
    cov_kernel<<<grid, NT, smem>>>(x, y, out);
}

// round 13
// speedup vs baseline: 1.1989x; 1.1989x over previous
#include <cuda_runtime.h>

#define IMG    1024
#define OUTD   1016
#define TILE_W 128
#define TILE_H 32
#define IN_H   (TILE_H + 8)    // 40 input rows
#define HS     136             // smem row stride (floats)
#define NT     320
#define NW     (NT / 32)       // 10 warps
#define STRIPH 16              // output rows per strip
#define NSTEP  (STRIPH + 4)    // 20 D-rows per strip (16 outputs + 4 warmup)

__device__ __forceinline__ float4 ld4g(const float* __restrict__ img, int gr, int gc) {
    float4 v = make_float4(0.f, 0.f, 0.f, 0.f);
    if (gr < IMG) {
        const float* row = img + (size_t)gr * IMG;
        if (gc + 3 < IMG) {
            v = *(const float4*)(row + gc);
        } else {
            if (gc     < IMG) v.x = row[gc];
            if (gc + 1 < IMG) v.y = row[gc + 1];
            if (gc + 2 < IMG) v.z = row[gc + 2];
        }
    }
    return v;
}

// Horizontal 5-sum of one 136-col row into hrow[0..131].
// Lane ln computes h[4ln..4ln+3] from its own float4 + right neighbor via 4
// shuffles; lane 31 replaces the (garbage) shuffle result with direct halo
// loads (cols 128..135) and also produces h[128..131]. 4 shuffles total.
__device__ __forceinline__ void hrow_sum(const float* __restrict__ img, int gr,
                                         int gc0, float* hrow, int ln) {
    const unsigned m = 0xFFFFFFFFu;
    float4 v = ld4g(img, gr, gc0 + 4 * ln);
    float4 nb;
    nb.x = __shfl_down_sync(m, v.x, 1);
    nb.y = __shfl_down_sync(m, v.y, 1);
    nb.z = __shfl_down_sync(m, v.z, 1);
    nb.w = __shfl_down_sync(m, v.w, 1);
    float4 e = make_float4(0.f, 0.f, 0.f, 0.f);
    if (ln == 31) {
        nb = ld4g(img, gr, gc0 + 128);   // cols 128..131 (lane 31's neighbor)
        e  = ld4g(img, gr, gc0 + 132);   // cols 132..135
    }
    float h0 = (v.x + v.y) + (v.z + v.w) + nb.x;
    float h1 = h0 - v.x + nb.y;
    float h2 = h1 - v.y + nb.z;
    float h3 = h2 - v.z + nb.w;
    *(float4*)(hrow + 4 * ln) = make_float4(h0, h1, h2, h3);
    if (ln == 31) {                      // h[128..131] from cols 128..135
        float g0 = (nb.x + nb.y) + (nb.z + nb.w) + e.x;
        float g1 = g0 - nb.x + e.y;
        float g2 = g1 - nb.y + e.z;
        float g3 = g2 - nb.z + e.w;
        *(float4*)(hrow + 128) = make_float4(g0, g1, g2, g3);
    }
}

__global__ __launch_bounds__(NT, 4) void cov_kernel(
    const float* __restrict__ x, const float* __restrict__ y,
    float* __restrict__ out)
{
    extern __shared__ float sm[];
    float* hA = sm;              // [IN_H][HS] : horizontal 5-sums of x (read-only after P1)
    float* hB = sm + IN_H * HS;  // [IN_H][HS] : horizontal 5-sums of y

    const int bx  = blockIdx.x * TILE_W;
    const int by  = blockIdx.y * TILE_H;
    const int n   = blockIdx.z;
    const int tid = threadIdx.x;
    const int wid = tid >> 5;
    const int ln  = tid & 31;

    const size_t ibase = (size_t)n * IMG * IMG;
    const float* xp = x + ibase;
    const float* yp = y + ibase;

    // ---- Phase 1: global load + horizontal 5-sums for x and y ----
    for (int r = wid; r < IN_H; r += NW) {
        const int gr = by + r;
        hrow_sum(xp, gr, bx, hA + r * HS, ln);
        hrow_sum(yp, gr, bx, hB + r * HS, ln);
    }
    __syncthreads();   // the only barrier: hA/hB are read-only from here on

    // ---- Phase 2 (fused): vertical 5-sums, deviation product, horizontal 5-sum
    // of D via 3 warp shuffles, vertical 5-sum of that via register ring, direct
    // global store. wid = strip*5 + wseg; a warp owns 32 D-columns
    // qr = wseg*28 + ln (4-col shuffle halo between segments) and NSTEP D-rows.
    {
        const unsigned FULL = 0xFFFFFFFFu;
        const int strip = wid / 5;               // 0..1
        const int wseg  = wid % 5;
        const int p0    = strip * STRIPH;        // 0 or 16
        const int qr    = wseg * 28 + ln;        // nominal D column (0..139)
        const int q     = qr < 131 ? qr : 131;   // clamp for safe smem reads

        const float* cA = hA + q;
        const float* cB = hB + q;
        float rgA[5], rgB[5], rd[5];
        #pragma unroll
        for (int t = 0; t < 5; ++t) {
            rgA[t] = cA[(p0 + t) * HS];
            rgB[t] = cB[(p0 + t) * HS];
            rd[t]  = 0.f;
        }
        float sA = ((rgA[0] + rgA[1]) + (rgA[2] + rgA[3])) + rgA[4];
        float sB = ((rgB[0] + rgB[1]) + (rgB[2] + rgB[3])) + rgB[4];
        float vd = 0.f;

        const int  gc     = bx + q + 2;
        const bool gcok   = (gc < IMG);
        const int  rowlim = IMG - (by + p0 + 2);     // #valid center rows
        const float* xc = xp + (size_t)(by + p0 + 2) * IMG + gc;
        const float* yc = yp + (size_t)(by + p0 + 2) * IMG + gc;

        // output col = qr (lanes 0..27 only); output row oy = by + p0 + k - 4
        const bool jout = (ln < 28) && (qr < TILE_W) && (bx + qr < OUTD);
        const int  klim = min(NSTEP, OUTD - by - p0 + 4);   // oy < OUTD
        float* ob = out + (size_t)n * OUTD * OUTD + bx + qr;

        #pragma unroll
        for (int k = 0; k < NSTEP; ++k) {
            const bool ok = gcok && (k < rowlim);
            float xv = ok ? xc[(size_t)k * IMG] : 0.f;   // L2-hit center re-read
            float yv = ok ? yc[(size_t)k * IMG] : 0.f;
            float d  = (xv - sA * 0.04f) * (yv - sB * 0.04f);

            // horizontal 5-sum of D across lanes: d[q]+..+d[q+4] in 3 shuffles
            float a  = d + __shfl_down_sync(FULL, d, 1);
            float hd = a + __shfl_down_sync(FULL, a, 2)
                         + __shfl_down_sync(FULL, d, 4);

            vd += hd - rd[k % 5];
            rd[k % 5] = hd;

            if (k >= 4 && k < klim && jout)
                ob[(size_t)(by + p0 + k - 4) * OUTD] = vd * 0.04f;

            if (k < NSTEP - 1) {
                float nwA = cA[(p0 + k + 5) * HS];
                sA += nwA - rgA[k % 5];  rgA[k % 5] = nwA;
                float nwB = cB[(p0 + k + 5) * HS];
                sB += nwB - rgB[k % 5];  rgB[k % 5] = nwB;
            }
        }
    }
}

extern "C" void kernel_launch(void* const* d_in, const int* in_sizes, int n_in,
                              void* d_out, int out_size) {
    const float* x = (const float*)d_in[0];
    const float* y = (const float*)d_in[1];
    // d_in[2] = mean_mask (uniform 1/25, folded into the 0.04f constants)
    float* out = (float*)d_out;

    const int smem = 2 * IN_H * HS * (int)sizeof(float);   // 43520 B
    cudaFuncSetAttribute(cov_kernel, cudaFuncAttributeMaxDynamicSharedMemorySize, smem);

    dim3 grid((OUTD + TILE_W - 1) / TILE_W,    // 8
              (OUTD + TILE_H - 1) / TILE_H,    // 32
              16);
    cov_kernel<<<grid, NT, smem>>>(x, y, out);
}

// round 14
// speedup vs baseline: 1.2148x; 1.0133x over previous
#include <cuda_runtime.h>

#define IMG    1024
#define OUTD   1016
#define TILE_W 120             // output cols per CTA (input span 128 = 32 lanes x 4)
#define TILE_H 40
#define IN_H   (TILE_H + 8)    // 48 input rows
#define HS     128             // smem row stride (floats); h[0..123] used
#define NT     320
#define NW     (NT / 32)       // 10 warps
#define STRIPH 8               // output rows per strip (5 strips x 2 warps)
#define NSTEP  (STRIPH + 4)    // 12 D-rows per strip

__device__ __forceinline__ float4 ld4g(const float* __restrict__ img, int gr, int gc) {
    float4 v = make_float4(0.f, 0.f, 0.f, 0.f);
    if (gr < IMG) {
        const float* row = img + (size_t)gr * IMG;
        if (gc + 3 < IMG) {
            v = *(const float4*)(row + gc);
        } else {
            if (gc     < IMG) v.x = row[gc];
            if (gc + 1 < IMG) v.y = row[gc + 1];
            if (gc + 2 < IMG) v.z = row[gc + 2];
        }
    }
    return v;
}

// Horizontal 5-sum of one 128-col input row (cols bx..bx+127) into hrow[0..127].
// Lane l computes h[4l..4l+3]; only h[0..123] are meaningful (lane 31's tail
// values are garbage but in-bounds and never read). 4 shuffles, no halo loads.
__device__ __forceinline__ void hrow_sum(const float* __restrict__ img, int gr,
                                         int gc0, float* hrow, int ln) {
    const unsigned m = 0xFFFFFFFFu;
    float4 v = ld4g(img, gr, gc0 + 4 * ln);
    float4 nb;
    nb.x = __shfl_down_sync(m, v.x, 1);
    nb.y = __shfl_down_sync(m, v.y, 1);
    nb.z = __shfl_down_sync(m, v.z, 1);
    nb.w = __shfl_down_sync(m, v.w, 1);
    float h0 = (v.x + v.y) + (v.z + v.w) + nb.x;
    float h1 = h0 - v.x + nb.y;
    float h2 = h1 - v.y + nb.z;
    float h3 = h2 - v.z + nb.w;
    *(float4*)(hrow + 4 * ln) = make_float4(h0, h1, h2, h3);
}

__global__ __launch_bounds__(NT, 4) void cov_kernel(
    const float* __restrict__ x, const float* __restrict__ y,
    float* __restrict__ out)
{
    extern __shared__ float sm[];
    float* hA = sm;              // [IN_H][HS] : horizontal 5-sums of x (read-only after P1)
    float* hB = sm + IN_H * HS;  // [IN_H][HS] : horizontal 5-sums of y

    const int bx  = blockIdx.x * TILE_W;
    const int by  = blockIdx.y * TILE_H;
    const int n   = blockIdx.z;
    const int tid = threadIdx.x;
    const int wid = tid >> 5;
    const int ln  = tid & 31;

    const size_t ibase = (size_t)n * IMG * IMG;
    const float* xp = x + ibase;
    const float* yp = y + ibase;

    // ---- Phase 1: global load + horizontal 5-sums for x and y ----
    for (int r = wid; r < IN_H; r += NW) {
        const int gr = by + r;
        hrow_sum(xp, gr, bx, hA + r * HS, ln);
        hrow_sum(yp, gr, bx, hB + r * HS, ln);
    }
    __syncthreads();   // the only barrier: hA/hB are read-only from here on

    // ---- Phase 2 (fused, 2 cols/thread): vertical 5-sums (rolling, smem
    // re-read for the -old term — hA/hB are read-only so no hazard), deviation
    // product, horizontal 5-sum of D via 3 shuffles per float2, vertical 5-sum
    // via float2 register ring, direct STG.64.
    // wid = strip*2 + w; warp covers D-cols q0 = 60w + 2l (+1); lanes 0..29
    // produce outputs (60 cols per warp), strips of 8 output rows.
    {
        const unsigned FULL = 0xFFFFFFFFu;
        const int strip = wid >> 1;              // 0..4
        const int w     = wid & 1;               // 0..1
        const int p0    = strip * STRIPH;        // 0,8,16,24,32
        const int q0    = 60 * w + 2 * ln;       // D column pair base (<=122)

        const float* cA = hA + q0;
        const float* cB = hB + q0;

        float2 sA, sB;
        {
            float2 a0 = *(const float2*)(cA + (p0  )*HS);
            float2 a1 = *(const float2*)(cA + (p0+1)*HS);
            float2 a2 = *(const float2*)(cA + (p0+2)*HS);
            float2 a3 = *(const float2*)(cA + (p0+3)*HS);
            float2 a4 = *(const float2*)(cA + (p0+4)*HS);
            sA = make_float2(((a0.x+a1.x)+(a2.x+a3.x))+a4.x,
                             ((a0.y+a1.y)+(a2.y+a3.y))+a4.y);
            float2 b0 = *(const float2*)(cB + (p0  )*HS);
            float2 b1 = *(const float2*)(cB + (p0+1)*HS);
            float2 b2 = *(const float2*)(cB + (p0+2)*HS);
            float2 b3 = *(const float2*)(cB + (p0+3)*HS);
            float2 b4 = *(const float2*)(cB + (p0+4)*HS);
            sB = make_float2(((b0.x+b1.x)+(b2.x+b3.x))+b4.x,
                             ((b0.y+b1.y)+(b2.y+b3.y))+b4.y);
        }

        float2 rd[5];
        #pragma unroll
        for (int t = 0; t < 5; ++t) rd[t] = make_float2(0.f, 0.f);
        float2 vd = make_float2(0.f, 0.f);

        const int  gc     = bx + q0 + 2;             // even; float2 in-row aligned
        const bool gcok   = (gc + 1 < IMG);
        const int  rowlim = IMG - (by + p0 + 2);     // #valid center rows
        const float* xc = xp + (size_t)(by + p0 + 2) * IMG + gc;
        const float* yc = yp + (size_t)(by + p0 + 2) * IMG + gc;

        const bool jout = (ln < 30) && (bx + q0 < OUTD);   // OUTD even: pair all-or-none
        const int  klim = min(NSTEP, OUTD - by - p0 + 4);  // oy < OUTD
        float* ob = out + (size_t)n * OUTD * OUTD + bx + q0;

        #pragma unroll
        for (int k = 0; k < NSTEP; ++k) {
            const bool ok = gcok && (k < rowlim);
            float2 xv = ok ? *(const float2*)(xc + (size_t)k * IMG)
                           : make_float2(0.f, 0.f);
            float2 yv = ok ? *(const float2*)(yc + (size_t)k * IMG)
                           : make_float2(0.f, 0.f);
            float d0 = (xv.x - sA.x * 0.04f) * (yv.x - sB.x * 0.04f);
            float d1 = (xv.y - sA.y * 0.04f) * (yv.y - sB.y * 0.04f);

            // horizontal 5-sum across the lane-interleaved pair columns:
            // h0 = d[q0..q0+4], h1 = d[q0+1..q0+5] in 3 shuffles
            float s  = d0 + d1;
            float s1 = __shfl_down_sync(FULL, s, 1);    // d[q0+2]+d[q0+3]
            float e0 = __shfl_down_sync(FULL, d0, 2);   // d[q0+4]
            float e1 = __shfl_down_sync(FULL, d1, 2);   // d[q0+5]
            float h0 = s + s1 + e0;
            float h1 = d1 + s1 + (e0 + e1);

            vd.x += h0 - rd[k % 5].x;
            vd.y += h1 - rd[k % 5].y;
            rd[k % 5] = make_float2(h0, h1);

            if (k >= 4 && k < klim && jout)
                *(float2*)(ob + (size_t)(by + p0 + k - 4) * OUTD) =
                    make_float2(vd.x * 0.04f, vd.y * 0.04f);

            if (k < NSTEP - 1) {
                const int pn = (p0 + k + 5) * HS, po = (p0 + k) * HS;
                float2 nwA = *(const float2*)(cA + pn);
                float2 olA = *(const float2*)(cA + po);
                sA.x += nwA.x - olA.x;  sA.y += nwA.y - olA.y;
                float2 nwB = *(const float2*)(cB + pn);
                float2 olB = *(const float2*)(cB + po);
                sB.x += nwB.x - olB.x;  sB.y += nwB.y - olB.y;
            }
        }
    }
}

extern "C" void kernel_launch(void* const* d_in, const int* in_sizes, int n_in,
                              void* d_out, int out_size) {
    const float* x = (const float*)d_in[0];
    const float* y = (const float*)d_in[1];
    // d_in[2] = mean_mask (uniform 1/25, folded into the 0.04f constants)
    float* out = (float*)d_out;

    const int smem = 2 * IN_H * HS * (int)sizeof(float);   // 49152 B
    cudaFuncSetAttribute(cov_kernel, cudaFuncAttributeMaxDynamicSharedMemorySize, smem);

    dim3 grid((OUTD + TILE_W - 1) / TILE_W,    // 9
              (OUTD + TILE_H - 1) / TILE_H,    // 26
              16);
    cov_kernel<<<grid, NT, smem>>>(x, y, out);
}

// round 15
// speedup vs baseline: 1.3034x; 1.0729x over previous
#include <cuda_runtime.h>

#define IMG    1024
#define OUTD   1016
#define TILE_W 128
#define TILE_H 42
#define IN_H   (TILE_H + 8)    // 50 input rows
#define HS     136             // smem row stride (floats)
#define NT     320
#define NW     (NT / 32)       // 10 warps
#define STRIPH 21              // output rows per strip
#define NSTEP  (STRIPH + 4)    // 25 D-rows per strip (21 outputs + 4 warmup)

__device__ __forceinline__ float4 ld4g(const float* __restrict__ img, int gr, int gc) {
    float4 v = make_float4(0.f, 0.f, 0.f, 0.f);
    if (gr < IMG) {
        const float* row = img + (size_t)gr * IMG;
        if (gc + 3 < IMG) {
            v = *(const float4*)(row + gc);
        } else {
            if (gc     < IMG) v.x = row[gc];
            if (gc + 1 < IMG) v.y = row[gc + 1];
            if (gc + 2 < IMG) v.z = row[gc + 2];
        }
    }
    return v;
}

// Warp-level horizontal 5-sum of one 136-float row: v = cols 4*ln..4*ln+3,
// v2 (lanes 0..1) = cols 128+4*ln..131+4*ln. Writes h[0..131].
__device__ __forceinline__ void hrow_sum(float4 v, float4 v2, float* hrow, int ln) {
    const unsigned m = 0xFFFFFFFFu;
    float4 n;
    n.x = __shfl_down_sync(m, v.x, 1);
    n.y = __shfl_down_sync(m, v.y, 1);
    n.z = __shfl_down_sync(m, v.z, 1);
    n.w = __shfl_down_sync(m, v.w, 1);
    float4 b0;
    b0.x = __shfl_sync(m, v2.x, 0);
    b0.y = __shfl_sync(m, v2.y, 0);
    b0.z = __shfl_sync(m, v2.z, 0);
    b0.w = __shfl_sync(m, v2.w, 0);
    if (ln == 31) n = b0;               // lane 31's right neighbor = cols 128..131

    float h0 = (v.x + v.y) + (v.z + v.w) + n.x;
    float h1 = h0 - v.x + n.y;
    float h2 = h1 - v.y + n.z;
    float h3 = h2 - v.z + n.w;
    *(float4*)(hrow + 4 * ln) = make_float4(h0, h1, h2, h3);

    float4 b1;
    b1.x = __shfl_sync(m, v2.x, 1);     // cols 132..135
    b1.y = __shfl_sync(m, v2.y, 1);
    b1.z = __shfl_sync(m, v2.z, 1);
    b1.w = __shfl_sync(m, v2.w, 1);
    if (ln == 0) {
        float g0 = (v2.x + v2.y) + (v2.z + v2.w) + b1.x;
        float g1 = g0 - v2.x + b1.y;
        float g2 = g1 - v2.y + b1.z;
        float g3 = g2 - v2.z + b1.w;
        *(float4*)(hrow + 128) = make_float4(g0, g1, g2, g3);
    }
}

__global__ __launch_bounds__(NT, 4) void cov_kernel(
    const float* __restrict__ x, const float* __restrict__ y,
    float* __restrict__ out)
{
    extern __shared__ float sm[];
    float* hA = sm;              // [IN_H][HS] : horizontal 5-sums of x (read-only after P1)
    float* hB = sm + IN_H * HS;  // [IN_H][HS] : horizontal 5-sums of y

    const int bx  = blockIdx.x * TILE_W;
    const int by  = blockIdx.y * TILE_H;
    const int n   = blockIdx.z;
    const int tid = threadIdx.x;
    const int wid = tid >> 5;
    const int ln  = tid & 31;

    const size_t ibase = (size_t)n * IMG * IMG;
    const float* xp = x + ibase;
    const float* yp = y + ibase;
    const float4 z4 = make_float4(0.f, 0.f, 0.f, 0.f);

    // ---- Phase 1: global load + warp-shuffle horizontal 5-sums for x and y ----
    for (int r = wid; r < IN_H; r += NW) {
        const int gr = by + r;
        float4 vx  = ld4g(xp, gr, bx + 4 * ln);
        float4 vx2 = (ln < 2) ? ld4g(xp, gr, bx + 128 + 4 * ln) : z4;
        hrow_sum(vx, vx2, hA + r * HS, ln);
        float4 vy  = ld4g(yp, gr, bx + 4 * ln);
        float4 vy2 = (ln < 2) ? ld4g(yp, gr, bx + 128 + 4 * ln) : z4;
        hrow_sum(vy, vy2, hB + r * HS, ln);
    }
    __syncthreads();   // the only barrier: hA/hB are read-only from here on

    // ---- Phase 2 (fused): vertical 5-sums, deviation product, horizontal 5-sum
    // of D via 3 warp shuffles, vertical 5-sum of that via register ring, direct
    // global store. wid = strip*5 + wseg; a warp owns 32 D-columns
    // qr = wseg*28 + ln (4-col shuffle halo between segments) and NSTEP D-rows.
    {
        const unsigned FULL = 0xFFFFFFFFu;
        const int strip = wid / 5;               // 0..1
        const int wseg  = wid % 5;
        const int p0    = strip * STRIPH;        // 0 or 21
        const int qr    = wseg * 28 + ln;        // nominal D column (0..139)
        const int q     = qr < 131 ? qr : 131;   // clamp for safe smem reads

        const float* cA = hA + q;
        const float* cB = hB + q;
        float rgA[5], rgB[5], rd[5];
        #pragma unroll
        for (int t = 0; t < 5; ++t) {
            rgA[t] = cA[(p0 + t) * HS];
            rgB[t] = cB[(p0 + t) * HS];
            rd[t]  = 0.f;
        }
        float sA = ((rgA[0] + rgA[1]) + (rgA[2] + rgA[3])) + rgA[4];
        float sB = ((rgB[0] + rgB[1]) + (rgB[2] + rgB[3])) + rgB[4];
        float vd = 0.f;

        const int  gc     = bx + q + 2;
        const bool gcok   = (gc < IMG);
        const int  rowlim = IMG - (by + p0 + 2);     // #valid center rows
        const float* xc = xp + (size_t)(by + p0 + 2) * IMG + gc;
        const float* yc = yp + (size_t)(by + p0 + 2) * IMG + gc;

        // output col = qr (lanes 0..27 only); output row oy = by + p0 + k - 4
        const bool jout = (ln < 28) && (qr < TILE_W) && (bx + qr < OUTD);
        const int  klim = min(NSTEP, OUTD - by - p0 + 4);   // oy < OUTD
        float* ob = out + (size_t)n * OUTD * OUTD + bx + qr;

        #pragma unroll
        for (int k = 0; k < NSTEP; ++k) {
            const bool ok = gcok && (k < rowlim);
            float xv = ok ? xc[(size_t)k * IMG] : 0.f;   // L2-hit center re-read
            float yv = ok ? yc[(size_t)k * IMG] : 0.f;
            float d  = (xv - sA * 0.04f) * (yv - sB * 0.04f);

            // horizontal 5-sum of D across lanes: d[q]+..+d[q+4] in 3 shuffles
            float a  = d + __shfl_down_sync(FULL, d, 1);
            float hd = a + __shfl_down_sync(FULL, a, 2)
                         + __shfl_down_sync(FULL, d, 4);

            vd += hd - rd[k % 5];
            rd[k % 5] = hd;

            if (k >= 4 && k < klim && jout)
                ob[(size_t)(by + p0 + k - 4) * OUTD] = vd * 0.04f;

            if (k < NSTEP - 1) {
                float nwA = cA[(p0 + k + 5) * HS];
                sA += nwA - rgA[k % 5];  rgA[k % 5] = nwA;
                float nwB = cB[(p0 + k + 5) * HS];
                sB += nwB - rgB[k % 5];  rgB[k % 5] = nwB;
            }
        }
    }
}

extern "C" void kernel_launch(void* const* d_in, const int* in_sizes, int n_in,
                              void* d_out, int out_size) {
    const float* x = (const float*)d_in[0];
    const float* y = (const float*)d_in[1];
    // d_in[2] = mean_mask (uniform 1/25, folded into the 0.04f constants)
    float* out = (float*)d_out;

    const int smem = 2 * IN_H * HS * (int)sizeof(float);   // 54400 B
    cudaFuncSetAttribute(cov_kernel, cudaFuncAttributeMaxDynamicSharedMemorySize, smem);

    dim3 grid((OUTD + TILE_W - 1) / TILE_W,    // 8
              (OUTD + TILE_H - 1) / TILE_H,    // 25
              16);
    cov_kernel<<<grid, NT, smem>>>(x, y, out);
}

// round 16
// speedup vs baseline: 1.3371x; 1.0258x over previous
#include <cuda_runtime.h>

#define IMG    1024
#define OUTD   1016
#define TILE_W 120             // output cols per CTA (input span 128 = 32 lanes x 4)
#define TILE_H 42
#define IN_H   (TILE_H + 8)    // 50 input rows
#define HS     128             // smem row stride (floats); h[0..123] valid
#define NT     320
#define NW     (NT / 32)       // 10 warps
#define STRIPH 21              // output rows per strip
#define NSTEP  (STRIPH + 4)    // 25 D-rows per strip (21 outputs + 4 warmup)

__device__ __forceinline__ float4 ld4g(const float* __restrict__ img, int gr, int gc) {
    float4 v = make_float4(0.f, 0.f, 0.f, 0.f);
    if (gr < IMG) {
        const float* row = img + (size_t)gr * IMG;
        if (gc + 3 < IMG) {
            v = *(const float4*)(row + gc);
        } else {
            if (gc     < IMG) v.x = row[gc];
            if (gc + 1 < IMG) v.y = row[gc + 1];
            if (gc + 2 < IMG) v.z = row[gc + 2];
        }
    }
    return v;
}

// Horizontal 5-sum of one 128-col input row (cols gc0..gc0+127) into hrow[0..127].
// Lane ln computes h[4ln..4ln+3]; h[0..123] are meaningful (lane 31's tail uses
// shuffle garbage but stays in-bounds and is never read). 4 shuffles, no halo.
__device__ __forceinline__ void hrow_sum(const float* __restrict__ img, int gr,
                                         int gc0, float* hrow, int ln) {
    const unsigned m = 0xFFFFFFFFu;
    float4 v = ld4g(img, gr, gc0 + 4 * ln);
    float4 nb;
    nb.x = __shfl_down_sync(m, v.x, 1);
    nb.y = __shfl_down_sync(m, v.y, 1);
    nb.z = __shfl_down_sync(m, v.z, 1);
    nb.w = __shfl_down_sync(m, v.w, 1);
    float h0 = (v.x + v.y) + (v.z + v.w) + nb.x;
    float h1 = h0 - v.x + nb.y;
    float h2 = h1 - v.y + nb.z;
    float h3 = h2 - v.z + nb.w;
    *(float4*)(hrow + 4 * ln) = make_float4(h0, h1, h2, h3);
}

__global__ __launch_bounds__(NT, 4) void cov_kernel(
    const float* __restrict__ x, const float* __restrict__ y,
    float* __restrict__ out)
{
    extern __shared__ float sm[];
    float* hA = sm;              // [IN_H][HS] : horizontal 5-sums of x (read-only after P1)
    float* hB = sm + IN_H * HS;  // [IN_H][HS] : horizontal 5-sums of y

    const int bx  = blockIdx.x * TILE_W;
    const int by  = blockIdx.y * TILE_H;
    const int n   = blockIdx.z;
    const int tid = threadIdx.x;
    const int wid = tid >> 5;
    const int ln  = tid & 31;

    const size_t ibase = (size_t)n * IMG * IMG;
    const float* xp = x + ibase;
    const float* yp = y + ibase;

    // ---- Phase 1: global load + horizontal 5-sums for x and y (halo-free) ----
    for (int r = wid; r < IN_H; r += NW) {
        const int gr = by + r;
        hrow_sum(xp, gr, bx, hA + r * HS, ln);
        hrow_sum(yp, gr, bx, hB + r * HS, ln);
    }
    __syncthreads();   // the only barrier: hA/hB are read-only from here on

    // ---- Phase 2 (fused): vertical 5-sums, deviation product, horizontal 5-sum
    // of D via 3 warp shuffles, vertical 5-sum of that via register ring, direct
    // global store. wid = strip*5 + wseg; a warp owns 32 D-columns
    // qr = wseg*28 + ln (4-col shuffle halo between segments) and NSTEP D-rows.
    {
        const unsigned FULL = 0xFFFFFFFFu;
        const int strip = wid / 5;               // 0..1
        const int wseg  = wid % 5;
        const int p0    = strip * STRIPH;        // 0 or 21
        const int qr    = wseg * 28 + ln;        // nominal D column (0..139)
        const int q     = qr < 123 ? qr : 123;   // clamp for safe smem reads

        const float* cA = hA + q;
        const float* cB = hB + q;
        float rgA[5], rgB[5], rd[5];
        #pragma unroll
        for (int t = 0; t < 5; ++t) {
            rgA[t] = cA[(p0 + t) * HS];
            rgB[t] = cB[(p0 + t) * HS];
            rd[t]  = 0.f;
        }
        float sA = ((rgA[0] + rgA[1]) + (rgA[2] + rgA[3])) + rgA[4];
        float sB = ((rgB[0] + rgB[1]) + (rgB[2] + rgB[3])) + rgB[4];
        float vd = 0.f;

        const int  gc     = bx + q + 2;
        const bool gcok   = (gc < IMG);
        const int  rowlim = IMG - (by + p0 + 2);     // #valid center rows
        const float* xc = xp + (size_t)(by + p0 + 2) * IMG + gc;
        const float* yc = yp + (size_t)(by + p0 + 2) * IMG + gc;

        // output col = qr (lanes 0..27 only); output row oy = by + p0 + k - 4
        const bool jout = (ln < 28) && (qr < TILE_W) && (bx + qr < OUTD);
        const int  klim = min(NSTEP, OUTD - by - p0 + 4);   // oy < OUTD
        float* ob = out + (size_t)n * OUTD * OUTD + bx + qr;

        #pragma unroll
        for (int k = 0; k < NSTEP; ++k) {
            const bool ok = gcok && (k < rowlim);
            float xv = ok ? xc[(size_t)k * IMG] : 0.f;   // L2-hit center re-read
            float yv = ok ? yc[(size_t)k * IMG] : 0.f;
            float d  = (xv - sA * 0.04f) * (yv - sB * 0.04f);

            // horizontal 5-sum of D across lanes: d[q]+..+d[q+4] in 3 shuffles
            float a  = d + __shfl_down_sync(FULL, d, 1);
            float hd = a + __shfl_down_sync(FULL, a, 2)
                         + __shfl_down_sync(FULL, d, 4);

            vd += hd - rd[k % 5];
            rd[k % 5] = hd;

            if (k >= 4 && k < klim && jout)
                ob[(size_t)(by + p0 + k - 4) * OUTD] = vd * 0.04f;

            if (k < NSTEP - 1) {
                float nwA = cA[(p0 + k + 5) * HS];
                sA += nwA - rgA[k % 5];  rgA[k % 5] = nwA;
                float nwB = cB[(p0 + k + 5) * HS];
                sB += nwB - rgB[k % 5];  rgB[k % 5] = nwB;
            }
        }
    }
}

extern "C" void kernel_launch(void* const* d_in, const int* in_sizes, int n_in,
                              void* d_out, int out_size) {
    const float* x = (const float*)d_in[0];
    const float* y = (const float*)d_in[1];
    // d_in[2] = mean_mask (uniform 1/25, folded into the 0.04f constants)
    float* out = (float*)d_out;

    const int smem = 2 * IN_H * HS * (int)sizeof(float);   // 51200 B
    cudaFuncSetAttribute(cov_kernel, cudaFuncAttributeMaxDynamicSharedMemorySize, smem);

    dim3 grid((OUTD + TILE_W - 1) / TILE_W,    // 9
              (OUTD + TILE_H - 1) / TILE_H,    // 25
              16);
    cov_kernel<<<grid, NT, smem>>>(x, y, out);
}